// round 2
// baseline (speedup 1.0000x reference)
#include <cuda_runtime.h>

#define NN  50000
#define EE  1600000
#define FIN 128
#define HH  32
#define CC  16

typedef unsigned long long u64;

// ---- scratch (device globals; no allocation allowed) ----
__device__ int   g_cnt[NN];        // per-dst edge count (no self-loop)
__device__ int   g_off[NN];        // CSR offsets
__device__ int   g_cur[NN];        // fill cursors
__device__ int   g_col[EE];        // src ids bucketed by dst
__device__ float g_dinv[NN];       // 1/sqrt(deg), deg = cnt+1
__device__ float g_xws[NN * HH];   // per-row dinv-prescaled features (reused both layers)
__device__ float g_h1[NN * HH];    // layer-1 activations

// ---- f32x2 helpers ----
__device__ __forceinline__ u64 fma2(u64 a, u64 b, u64 c) {
    u64 d; asm("fma.rn.f32x2 %0, %1, %2, %3;" : "=l"(d) : "l"(a), "l"(b), "l"(c)); return d;
}
__device__ __forceinline__ u64 pack2(float x, float y) {
    u64 d; asm("mov.b64 %0, {%1, %2};" : "=l"(d) : "f"(x), "f"(y)); return d;
}
__device__ __forceinline__ u64 mul2(u64 a, u64 b) {
    u64 d; asm("mul.rn.f32x2 %0, %1, %2;" : "=l"(d) : "l"(a), "l"(b)); return d;
}

// ================================================================ CSR build
__global__ void k_zero() {
    int i = blockIdx.x * blockDim.x + threadIdx.x;
    if (i < NN) g_cnt[i] = 0;
}

__global__ void k_count(const int* __restrict__ dst) {
    int e = blockIdx.x * blockDim.x + threadIdx.x;
    if (e < EE) atomicAdd(&g_cnt[dst[e]], 1);
}

#define SCAN_T 1024
__global__ void k_scan() {
    __shared__ int ssum[SCAN_T];
    int tid = threadIdx.x;
    const int per = (NN + SCAN_T - 1) / SCAN_T;   // 49
    int base = tid * per;
    int sum = 0;
    for (int i = 0; i < per; i++) {
        int idx = base + i;
        if (idx < NN) sum += g_cnt[idx];
    }
    ssum[tid] = sum;
    __syncthreads();
    for (int off = 1; off < SCAN_T; off <<= 1) {
        int v = (tid >= off) ? ssum[tid - off] : 0;
        __syncthreads();
        ssum[tid] += v;
        __syncthreads();
    }
    int run = (tid == 0) ? 0 : ssum[tid - 1];     // exclusive prefix of this chunk
    for (int i = 0; i < per; i++) {
        int idx = base + i;
        if (idx < NN) {
            int c = g_cnt[idx];
            g_off[idx] = run;
            g_cur[idx] = run;
            g_dinv[idx] = rsqrtf((float)(c + 1));   // +1 self-loop
            run += c;
        }
    }
}

__global__ void k_fill(const int* __restrict__ src, const int* __restrict__ dst) {
    int e = blockIdx.x * blockDim.x + threadIdx.x;
    if (e < EE) {
        int d = dst[e];
        int pos = atomicAdd(&g_cur[d], 1);
        g_col[pos] = src[e];
    }
}

// ================================================================ GEMM1: xws = (x @ W1) * dinv[row]
// thread-per-row, 16 f32x2 accumulators, W1 broadcast from smem via LDS.128
__global__ void k_gemm1(const float* __restrict__ x, const float* __restrict__ W1) {
    __shared__ u64 Wp[FIN * HH / 2];   // 2048 pairs = 16KB, Wp[k*16+p] = (W[k][2p], W[k][2p+1])
    int tid = threadIdx.x;
    for (int i = tid; i < FIN * HH / 2; i += 256) Wp[i] = ((const u64*)W1)[i];
    __syncthreads();

    int row = blockIdx.x * 256 + tid;
    if (row >= NN) return;
    const float4* xr = (const float4*)(x + row * FIN);
    u64 acc[16];
#pragma unroll
    for (int p = 0; p < 16; p++) acc[p] = 0ull;

    for (int kb = 0; kb < FIN / 4; kb++) {
        float4 xv = xr[kb];
        const ulonglong2* w2 = (const ulonglong2*)(Wp + (4 * kb) * 16);
        u64 xx;
        xx = pack2(xv.x, xv.x);
#pragma unroll
        for (int q = 0; q < 8; q++) { ulonglong2 w = w2[q];      acc[2*q] = fma2(xx, w.x, acc[2*q]); acc[2*q+1] = fma2(xx, w.y, acc[2*q+1]); }
        xx = pack2(xv.y, xv.y);
#pragma unroll
        for (int q = 0; q < 8; q++) { ulonglong2 w = w2[8 + q];  acc[2*q] = fma2(xx, w.x, acc[2*q]); acc[2*q+1] = fma2(xx, w.y, acc[2*q+1]); }
        xx = pack2(xv.z, xv.z);
#pragma unroll
        for (int q = 0; q < 8; q++) { ulonglong2 w = w2[16 + q]; acc[2*q] = fma2(xx, w.x, acc[2*q]); acc[2*q+1] = fma2(xx, w.y, acc[2*q+1]); }
        xx = pack2(xv.w, xv.w);
#pragma unroll
        for (int q = 0; q < 8; q++) { ulonglong2 w = w2[24 + q]; acc[2*q] = fma2(xx, w.x, acc[2*q]); acc[2*q+1] = fma2(xx, w.y, acc[2*q+1]); }
    }

    float di = g_dinv[row];
    u64 dd = pack2(di, di);
    u64* orow = (u64*)(g_xws + row * HH);
#pragma unroll
    for (int p = 0; p < 16; p++) orow[p] = mul2(acc[p], dd);
}

// ================================================================ CSR gather core
// 8 lanes per dst node; lane l owns float4 column chunk l. Edges consumed in
// batches of 8 (one per lane), redistributed via shfl(width=8) so the 8
// dependent gathers issue back-to-back (MLP=8 per group).
__device__ __forceinline__ float4 gather_acc(int g, int c4, unsigned gmask, int l) {
    int beg = g_off[g];
    int end = beg + g_cnt[g];
    float4 acc = *(const float4*)(g_xws + g * HH + c4);   // self-loop seed
    int i = beg;
    while (i + 8 <= end) {
        int e = g_col[i + l];
#pragma unroll
        for (int j = 0; j < 8; j++) {
            int s = __shfl_sync(gmask, e, j, 8);
            float4 v = *(const float4*)(g_xws + s * HH + c4);
            acc.x += v.x; acc.y += v.y; acc.z += v.z; acc.w += v.w;
        }
        i += 8;
    }
    for (; i < end; i++) {
        int s = g_col[i];
        float4 v = *(const float4*)(g_xws + s * HH + c4);
        acc.x += v.x; acc.y += v.y; acc.z += v.z; acc.w += v.w;
    }
    return acc;
}

// layer 1: h1 = tanh(dinv * agg + b1)
__global__ void k_gather1(const float* __restrict__ b1) {
    int idx = blockIdx.x * blockDim.x + threadIdx.x;
    int g = idx >> 3;
    if (g >= NN) return;
    int l = idx & 7, c4 = l << 2;
    unsigned gmask = 0xffu << (threadIdx.x & 24);
    float4 acc = gather_acc(g, c4, gmask, l);
    float di = g_dinv[g];
    float4 b = *(const float4*)(b1 + c4);
    float4 h;
    h.x = tanhf(di * acc.x + b.x);
    h.y = tanhf(di * acc.y + b.y);
    h.z = tanhf(di * acc.z + b.z);
    h.w = tanhf(di * acc.w + b.w);
    *(float4*)(g_h1 + g * HH + c4) = h;
}

// layer 2: h = tanh(dinv * agg + b2), written straight into out's h-region
__global__ void k_gather2(const float* __restrict__ b2, float* __restrict__ out) {
    int idx = blockIdx.x * blockDim.x + threadIdx.x;
    int g = idx >> 3;
    if (g >= NN) return;
    int l = idx & 7, c4 = l << 2;
    unsigned gmask = 0xffu << (threadIdx.x & 24);
    float4 acc = gather_acc(g, c4, gmask, l);
    float di = g_dinv[g];
    float4 b = *(const float4*)(b2 + c4);
    float4 h;
    h.x = tanhf(di * acc.x + b.x);
    h.y = tanhf(di * acc.y + b.y);
    h.z = tanhf(di * acc.z + b.z);
    h.w = tanhf(di * acc.w + b.w);
    *(float4*)(out + NN * CC + g * HH + c4) = h;
}

// ================================================================ GEMM2: xws = (h1 @ W2) * dinv[row]
__global__ void k_gemm2(const float* __restrict__ W2) {
    __shared__ float Ws[HH * HH];
    int tid = threadIdx.x;
    for (int i = tid; i < HH * HH; i += 256) Ws[i] = W2[i];
    __syncthreads();
    int warp = tid >> 5, lane = tid & 31;
    int row = blockIdx.x * 8 + warp;
    if (row >= NN) return;
    float hv = g_h1[row * HH + lane];
    float acc = 0.0f;
#pragma unroll
    for (int j = 0; j < 32; j++) {
        float hj = __shfl_sync(0xffffffffu, hv, j);
        acc += hj * Ws[j * HH + lane];
    }
    g_xws[row * HH + lane] = acc * g_dinv[row];
}

// ================================================================ classifier: out = h @ Wc + bc
__global__ void k_cls(const float* __restrict__ Wc, const float* __restrict__ bc,
                      float* __restrict__ out) {
    __shared__ float Wcs[HH * CC];
    int tid = threadIdx.x;
    for (int i = tid; i < HH * CC; i += 256) Wcs[i] = Wc[i];
    __syncthreads();
    int warp = tid >> 5, lane = tid & 31;
    int row = blockIdx.x * 8 + warp;
    if (row >= NN) return;
    float h = out[NN * CC + row * HH + lane];
    int cl = lane & (CC - 1);
    float acc = bc[cl];
#pragma unroll
    for (int j = 0; j < 32; j++) {
        float hj = __shfl_sync(0xffffffffu, h, j);
        acc += hj * Wcs[j * CC + cl];
    }
    if (lane < CC) out[row * CC + lane] = acc;
}

// ================================================================ launch
extern "C" void kernel_launch(void* const* d_in, const int* in_sizes, int n_in,
                              void* d_out, int out_size) {
    const float* x  = (const float*)d_in[0];
    const int*   ei = (const int*)  d_in[1];
    const float* W1 = (const float*)d_in[2];
    const float* b1 = (const float*)d_in[3];
    const float* W2 = (const float*)d_in[4];
    const float* b2 = (const float*)d_in[5];
    const float* Wc = (const float*)d_in[6];
    const float* bc = (const float*)d_in[7];
    const int* src = ei;          // edge_index[0]
    const int* dst = ei + EE;     // edge_index[1]
    float* out = (float*)d_out;

    k_zero   <<<(NN + 255) / 256, 256>>>();
    k_count  <<<(EE + 255) / 256, 256>>>(dst);
    k_scan   <<<1, SCAN_T>>>();
    k_fill   <<<(EE + 255) / 256, 256>>>(src, dst);

    k_gemm1  <<<(NN + 255) / 256, 256>>>(x, W1);
    k_gather1<<<(NN * 8 + 255) / 256, 256>>>(b1);

    k_gemm2  <<<(NN + 7) / 8, 256>>>(W2);
    k_gather2<<<(NN * 8 + 255) / 256, 256>>>(b2, out);

    k_cls    <<<(NN + 7) / 8, 256>>>(Wc, bc, out);
}

// round 3
// speedup vs baseline: 1.4609x; 1.4609x over previous
#include <cuda_runtime.h>

#define NN  50000
#define EE  1600000
#define FIN 128
#define HH  32
#define CC  16

typedef unsigned long long u64;

// ---- scratch (device globals; no allocation allowed) ----
__device__ float g_deg[NN];
__device__ float g_dinv[NN];
__device__ float g_xws[NN * HH];   // dinv-prescaled features (both layers)
__device__ float g_agg[NN * HH];   // aggregation accumulator

// ---- f32x2 helpers ----
__device__ __forceinline__ u64 fma2(u64 a, u64 b, u64 c) {
    u64 d; asm("fma.rn.f32x2 %0, %1, %2, %3;" : "=l"(d) : "l"(a), "l"(b), "l"(c)); return d;
}
__device__ __forceinline__ u64 pack2(float x, float y) {
    u64 d; asm("mov.b64 %0, {%1, %2};" : "=l"(d) : "f"(x), "f"(y)); return d;
}
__device__ __forceinline__ u64 mul2(u64 a, u64 b) {
    u64 d; asm("mul.rn.f32x2 %0, %1, %2;" : "=l"(d) : "l"(a), "l"(b)); return d;
}

// ================================================================ degrees
__global__ void k_init_deg() {
    int i = blockIdx.x * blockDim.x + threadIdx.x;
    if (i < NN) g_deg[i] = 1.0f;                 // self-loop
}

__global__ void k_count_deg(const int* __restrict__ dst) {
    int e = blockIdx.x * blockDim.x + threadIdx.x;
    if (e < EE) atomicAdd(&g_deg[dst[e]], 1.0f);
}

__global__ void k_dinv() {
    int i = blockIdx.x * blockDim.x + threadIdx.x;
    if (i < NN) g_dinv[i] = rsqrtf(g_deg[i]);
}

// ================================================================ GEMM1: xws = agg = (x @ W1) * dinv[row]
// thread-per-row, 16 f32x2 accumulators, W1 broadcast from smem via LDS.128
__global__ void k_gemm1(const float* __restrict__ x, const float* __restrict__ W1) {
    __shared__ u64 Wp[FIN * HH / 2];   // 16KB: Wp[k*16+p] = (W[k][2p], W[k][2p+1])
    int tid = threadIdx.x;
    for (int i = tid; i < FIN * HH / 2; i += 256) Wp[i] = ((const u64*)W1)[i];
    __syncthreads();

    int row = blockIdx.x * 256 + tid;
    if (row >= NN) return;
    const float4* xr = (const float4*)(x + row * FIN);
    u64 acc[16];
#pragma unroll
    for (int p = 0; p < 16; p++) acc[p] = 0ull;

    for (int kb = 0; kb < FIN / 4; kb++) {
        float4 xv = xr[kb];
        const ulonglong2* w2 = (const ulonglong2*)(Wp + (4 * kb) * 16);
        u64 xx;
        xx = pack2(xv.x, xv.x);
#pragma unroll
        for (int q = 0; q < 8; q++) { ulonglong2 w = w2[q];      acc[2*q] = fma2(xx, w.x, acc[2*q]); acc[2*q+1] = fma2(xx, w.y, acc[2*q+1]); }
        xx = pack2(xv.y, xv.y);
#pragma unroll
        for (int q = 0; q < 8; q++) { ulonglong2 w = w2[8 + q];  acc[2*q] = fma2(xx, w.x, acc[2*q]); acc[2*q+1] = fma2(xx, w.y, acc[2*q+1]); }
        xx = pack2(xv.z, xv.z);
#pragma unroll
        for (int q = 0; q < 8; q++) { ulonglong2 w = w2[16 + q]; acc[2*q] = fma2(xx, w.x, acc[2*q]); acc[2*q+1] = fma2(xx, w.y, acc[2*q+1]); }
        xx = pack2(xv.w, xv.w);
#pragma unroll
        for (int q = 0; q < 8; q++) { ulonglong2 w = w2[24 + q]; acc[2*q] = fma2(xx, w.x, acc[2*q]); acc[2*q+1] = fma2(xx, w.y, acc[2*q+1]); }
    }

    float di = g_dinv[row];
    u64 dd = pack2(di, di);
    u64* orow = (u64*)(g_xws + row * HH);
    u64* arow = (u64*)(g_agg + row * HH);
#pragma unroll
    for (int p = 0; p < 16; p++) {
        u64 v = mul2(acc[p], dd);
        orow[p] = v;
        arow[p] = v;          // seed with self-loop contribution
    }
}

// ================================================================ edge scatter: agg[dst] += xws[src]
// 8 lanes per edge, each lane one float4, vectorized L2 reduction.
__global__ void k_scatter(const int* __restrict__ src, const int* __restrict__ dst) {
    int idx = blockIdx.x * blockDim.x + threadIdx.x;
    if (idx >= EE * 8) return;
    int e  = idx >> 3;
    int c4 = (idx & 7) << 2;
    int s = __ldg(src + e);
    int d = __ldg(dst + e);
    float4 v = *(const float4*)(g_xws + s * HH + c4);
    float* p = g_agg + d * HH + c4;
    asm volatile("red.global.add.v4.f32 [%0], {%1,%2,%3,%4};"
                 :: "l"(p), "f"(v.x), "f"(v.y), "f"(v.z), "f"(v.w)
                 : "memory");
}

// ================================================================ GEMM2 (layer-1 epilogue fused):
// h = tanh(dinv*agg + b1); xws = agg = (h @ W2) * dinv[row]
__global__ void k_gemm2(const float* __restrict__ b1, const float* __restrict__ W2) {
    __shared__ float Ws[HH * HH];
    int tid = threadIdx.x;
    for (int i = tid; i < HH * HH; i += 256) Ws[i] = W2[i];
    __syncthreads();
    int warp = tid >> 5, lane = tid & 31;
    int row = blockIdx.x * 8 + warp;
    if (row >= NN) return;
    float di = g_dinv[row];
    float h = tanhf(di * g_agg[row * HH + lane] + b1[lane]);
    float acc = 0.0f;
#pragma unroll
    for (int j = 0; j < 32; j++) {
        float hj = __shfl_sync(0xffffffffu, h, j);
        acc += hj * Ws[j * HH + lane];
    }
    float v = acc * di;
    g_xws[row * HH + lane] = v;
    g_agg[row * HH + lane] = v;
}

// ================================================================ layer-2 epilogue + classifier
// h = tanh(dinv*agg + b2) -> out[N*CC ..]; out[0..] = h @ Wc + bc
__global__ void k_fin2(const float* __restrict__ b2, const float* __restrict__ Wc,
                       const float* __restrict__ bc, float* __restrict__ out) {
    __shared__ float Wcs[HH * CC];
    int tid = threadIdx.x;
    for (int i = tid; i < HH * CC; i += 256) Wcs[i] = Wc[i];
    __syncthreads();
    int warp = tid >> 5, lane = tid & 31;
    int row = blockIdx.x * 8 + warp;
    if (row >= NN) return;
    float di = g_dinv[row];
    float h = tanhf(di * g_agg[row * HH + lane] + b2[lane]);
    out[NN * CC + row * HH + lane] = h;      // second output: h [N,32]
    int cl = lane & (CC - 1);
    float acc = bc[cl];
#pragma unroll
    for (int j = 0; j < 32; j++) {
        float hj = __shfl_sync(0xffffffffu, h, j);
        acc += hj * Wcs[j * CC + cl];
    }
    if (lane < CC) out[row * CC + lane] = acc;   // first output: out [N,16]
}

// ================================================================ launch
extern "C" void kernel_launch(void* const* d_in, const int* in_sizes, int n_in,
                              void* d_out, int out_size) {
    const float* x  = (const float*)d_in[0];
    const int*   ei = (const int*)  d_in[1];
    const float* W1 = (const float*)d_in[2];
    const float* b1 = (const float*)d_in[3];
    const float* W2 = (const float*)d_in[4];
    const float* b2 = (const float*)d_in[5];
    const float* Wc = (const float*)d_in[6];
    const float* bc = (const float*)d_in[7];
    const int* src = ei;          // edge_index[0]
    const int* dst = ei + EE;     // edge_index[1]
    float* out = (float*)d_out;

    k_init_deg <<<(NN + 255) / 256, 256>>>();
    k_count_deg<<<(EE + 255) / 256, 256>>>(dst);
    k_dinv     <<<(NN + 255) / 256, 256>>>();

    k_gemm1    <<<(NN + 255) / 256, 256>>>(x, W1);
    k_scatter  <<<(EE * 8 + 255) / 256, 256>>>(src, dst);

    k_gemm2    <<<(NN + 7) / 8, 256>>>(b1, W2);
    k_scatter  <<<(EE * 8 + 255) / 256, 256>>>(src, dst);

    k_fin2     <<<(NN + 7) / 8, 256>>>(b2, Wc, bc, out);
}

// round 4
// speedup vs baseline: 1.4667x; 1.0040x over previous
#include <cuda_runtime.h>

#define NN  50000
#define EE  1600000
#define FIN 128
#define HH  32
#define CC  16

typedef unsigned long long u64;

// ---- scratch (device globals; no allocation allowed) ----
__device__ float g_deg[NN];
__device__ float g_dinv[NN];
__device__ float g_xws[NN * HH];   // dinv-prescaled features (both layers)
__device__ float g_agg[NN * HH];   // aggregation accumulator

// ---- f32x2 helpers ----
__device__ __forceinline__ u64 fma2(u64 a, u64 b, u64 c) {
    u64 d; asm("fma.rn.f32x2 %0, %1, %2, %3;" : "=l"(d) : "l"(a), "l"(b), "l"(c)); return d;
}
__device__ __forceinline__ u64 pack2(float x, float y) {
    u64 d; asm("mov.b64 %0, {%1, %2};" : "=l"(d) : "f"(x), "f"(y)); return d;
}
__device__ __forceinline__ u64 mul2(u64 a, u64 b) {
    u64 d; asm("mul.rn.f32x2 %0, %1, %2;" : "=l"(d) : "l"(a), "l"(b)); return d;
}

// ================================================================ degrees
__global__ void k_init_deg() {
    int i = blockIdx.x * blockDim.x + threadIdx.x;
    if (i < NN) g_deg[i] = 1.0f;                 // self-loop
}

__global__ void k_count_deg(const int* __restrict__ dst) {
    int e = blockIdx.x * blockDim.x + threadIdx.x;
    if (e < EE) atomicAdd(&g_deg[dst[e]], 1.0f);
}

__global__ void k_dinv() {
    int i = blockIdx.x * blockDim.x + threadIdx.x;
    if (i < NN) g_dinv[i] = rsqrtf(g_deg[i]);
}

// ================================================================ GEMM1: xws = agg = (x @ W1) * dinv[row]
// 128 threads / 128 rows per block. x staged through padded smem (coalesced
// LDG, conflict-free LDS); W1 as f32x2 pairs broadcast from smem; 16 f32x2 accs.
__global__ void __launch_bounds__(128) k_gemm1(const float* __restrict__ x,
                                               const float* __restrict__ W1) {
    __shared__ u64   Wp[FIN * HH / 2];     // 16KB: Wp[k*16+p] = (W[k][2p], W[k][2p+1])
    __shared__ float xs[128][33];          // 16.9KB, odd stride -> conflict-free
    int tid = threadIdx.x;
    for (int i = tid; i < FIN * HH / 2; i += 128) Wp[i] = ((const u64*)W1)[i];

    int row0 = blockIdx.x * 128;
    int row  = row0 + tid;
    u64 acc[16];
#pragma unroll
    for (int p = 0; p < 16; p++) acc[p] = 0ull;

    for (int kb = 0; kb < 4; kb++) {       // 4 chunks of 32 columns
        __syncthreads();
        // stage x[row0 .. row0+127][kb*32 .. kb*32+31], coalesced float4
        for (int q = tid; q < 1024; q += 128) {
            int r  = q >> 3;
            int c4 = (q & 7) << 2;
            int gr = row0 + r;
            float4 v = make_float4(0.f, 0.f, 0.f, 0.f);
            if (gr < NN) v = *(const float4*)(x + gr * FIN + kb * 32 + c4);
            xs[r][c4 + 0] = v.x;
            xs[r][c4 + 1] = v.y;
            xs[r][c4 + 2] = v.z;
            xs[r][c4 + 3] = v.w;
        }
        __syncthreads();
#pragma unroll
        for (int k = 0; k < 32; k++) {
            float xv = xs[tid][k];
            u64 xx = pack2(xv, xv);
            const ulonglong2* w2 = (const ulonglong2*)(Wp + (kb * 32 + k) * 16);
#pragma unroll
            for (int q = 0; q < 8; q++) {
                ulonglong2 w = w2[q];
                acc[2*q]   = fma2(xx, w.x, acc[2*q]);
                acc[2*q+1] = fma2(xx, w.y, acc[2*q+1]);
            }
        }
    }

    if (row >= NN) return;
    float di = g_dinv[row];
    u64 dd = pack2(di, di);
    u64* orow = (u64*)(g_xws + row * HH);
    u64* arow = (u64*)(g_agg + row * HH);
#pragma unroll
    for (int p = 0; p < 16; p++) {
        u64 v = mul2(acc[p], dd);
        orow[p] = v;
        arow[p] = v;          // seed with self-loop contribution
    }
}

// ================================================================ edge scatter: agg[dst] += xws[src]
// 8 lanes per edge, each lane one float4, vectorized L2 reduction.
__global__ void k_scatter(const int* __restrict__ src, const int* __restrict__ dst) {
    int idx = blockIdx.x * blockDim.x + threadIdx.x;
    if (idx >= EE * 8) return;
    int e  = idx >> 3;
    int c4 = (idx & 7) << 2;
    int s = __ldg(src + e);
    int d = __ldg(dst + e);
    float4 v = *(const float4*)(g_xws + s * HH + c4);
    float* p = g_agg + d * HH + c4;
    asm volatile("red.global.add.v4.f32 [%0], {%1,%2,%3,%4};"
                 :: "l"(p), "f"(v.x), "f"(v.y), "f"(v.z), "f"(v.w)
                 : "memory");
}

// ================================================================ GEMM2 (layer-1 epilogue fused):
// h = tanh(dinv*agg + b1); xws = agg = (h @ W2) * dinv[row]
__global__ void k_gemm2(const float* __restrict__ b1, const float* __restrict__ W2) {
    __shared__ float Ws[HH * HH];
    int tid = threadIdx.x;
    for (int i = tid; i < HH * HH; i += 256) Ws[i] = W2[i];
    __syncthreads();
    int warp = tid >> 5, lane = tid & 31;
    int row = blockIdx.x * 8 + warp;
    if (row >= NN) return;
    float di = g_dinv[row];
    float h = tanhf(di * g_agg[row * HH + lane] + b1[lane]);
    float acc = 0.0f;
#pragma unroll
    for (int j = 0; j < 32; j++) {
        float hj = __shfl_sync(0xffffffffu, h, j);
        acc += hj * Ws[j * HH + lane];
    }
    float v = acc * di;
    g_xws[row * HH + lane] = v;
    g_agg[row * HH + lane] = v;
}

// ================================================================ layer-2 epilogue + classifier
// h = tanh(dinv*agg + b2) -> out[N*CC ..]; out[0..] = h @ Wc + bc
__global__ void k_fin2(const float* __restrict__ b2, const float* __restrict__ Wc,
                       const float* __restrict__ bc, float* __restrict__ out) {
    __shared__ float Wcs[HH * CC];
    int tid = threadIdx.x;
    for (int i = tid; i < HH * CC; i += 256) Wcs[i] = Wc[i];
    __syncthreads();
    int warp = tid >> 5, lane = tid & 31;
    int row = blockIdx.x * 8 + warp;
    if (row >= NN) return;
    float di = g_dinv[row];
    float h = tanhf(di * g_agg[row * HH + lane] + b2[lane]);
    out[NN * CC + row * HH + lane] = h;      // second output: h [N,32]
    int cl = lane & (CC - 1);
    float acc = bc[cl];
#pragma unroll
    for (int j = 0; j < 32; j++) {
        float hj = __shfl_sync(0xffffffffu, h, j);
        acc += hj * Wcs[j * CC + cl];
    }
    if (lane < CC) out[row * CC + lane] = acc;   // first output: out [N,16]
}

// ================================================================ launch
extern "C" void kernel_launch(void* const* d_in, const int* in_sizes, int n_in,
                              void* d_out, int out_size) {
    const float* x  = (const float*)d_in[0];
    const int*   ei = (const int*)  d_in[1];
    const float* W1 = (const float*)d_in[2];
    const float* b1 = (const float*)d_in[3];
    const float* W2 = (const float*)d_in[4];
    const float* b2 = (const float*)d_in[5];
    const float* Wc = (const float*)d_in[6];
    const float* bc = (const float*)d_in[7];
    const int* src = ei;          // edge_index[0]
    const int* dst = ei + EE;     // edge_index[1]
    float* out = (float*)d_out;

    k_init_deg <<<(NN + 255) / 256, 256>>>();
    k_count_deg<<<(EE + 255) / 256, 256>>>(dst);
    k_dinv     <<<(NN + 255) / 256, 256>>>();

    k_gemm1    <<<(NN + 127) / 128, 128>>>(x, W1);
    k_scatter  <<<(EE * 8 + 255) / 256, 256>>>(src, dst);

    k_gemm2    <<<(NN + 7) / 8, 256>>>(b1, W2);
    k_scatter  <<<(EE * 8 + 255) / 256, 256>>>(src, dst);

    k_fin2     <<<(NN + 7) / 8, 256>>>(b2, Wc, bc, out);
}